// round 7
// baseline (speedup 1.0000x reference)
#include <cuda_runtime.h>
#include <cuda_bf16.h>
#include <math.h>
#include <stdint.h>

// Problem constants
#define BATCH   2
#define SEQ     2048
#define HID     3072
#define NH      32
#define NKV     8
#define HD      96
#define OPSZ    4608          // NH*HD + 2*NKV*HD
#define MROWS   4096          // BATCH*SEQ
#define QK_SCALE 0.10206207261596577f  // 1/sqrt(96)

// ---------------- scratch (device globals, no allocation) ----------------
__device__ float g_qkv  [(size_t)MROWS * OPSZ];
__device__ float g_q    [(size_t)BATCH * NH  * SEQ * HD];
__device__ float g_k    [(size_t)BATCH * NKV * SEQ * HD];
__device__ float g_v    [(size_t)BATCH * NKV * SEQ * HD];  // TRANSPOSED: [b,kvh][d][s]
__device__ float g_att  [(size_t)MROWS * HID];
__device__ float g_hs_r [(size_t)MROWS * HID];             // tf32-rounded hidden_states
__device__ float g_wqkvt[(size_t)OPSZ * HID];              // Wqkv^T [n][k], tf32-rounded
__device__ float g_wot  [(size_t)HID * HID];               // Wo^T   [n][k], tf32-rounded

// ============================================================
//          TF32 MMA + ldmatrix + cp.async helpers
// ============================================================
__device__ __forceinline__ uint32_t f2tf32(float x) {
    uint32_t r;
    asm("cvt.rna.tf32.f32 %0, %1;" : "=r"(r) : "f"(x));
    return r;
}
__device__ __forceinline__ float f2tf32f(float x) {
    return __uint_as_float(f2tf32(x));
}

__device__ __forceinline__ void mma_tf32(float* c, const uint32_t* a, const uint32_t* b) {
    asm volatile(
        "mma.sync.aligned.m16n8k8.row.col.f32.tf32.tf32.f32 "
        "{%0,%1,%2,%3}, {%4,%5,%6,%7}, {%8,%9}, {%0,%1,%2,%3};\n"
        : "+f"(c[0]), "+f"(c[1]), "+f"(c[2]), "+f"(c[3])
        : "r"(a[0]), "r"(a[1]), "r"(a[2]), "r"(a[3]),
          "r"(b[0]), "r"(b[1]));
}

__device__ __forceinline__ void ldmx4(uint32_t* r, uint32_t addr) {
    asm volatile("ldmatrix.sync.aligned.m8n8.x4.shared.b16 {%0,%1,%2,%3}, [%4];"
        : "=r"(r[0]), "=r"(r[1]), "=r"(r[2]), "=r"(r[3]) : "r"(addr));
}

__device__ __forceinline__ void cp16(uint32_t dst, const void* src) {
    asm volatile("cp.async.cg.shared.global [%0], [%1], 16;" :: "r"(dst), "l"(src));
}
__device__ __forceinline__ void cp_commit() {
    asm volatile("cp.async.commit_group;");
}
template<int N> __device__ __forceinline__ void cp_wait() {
    asm volatile("cp.async.wait_group %0;" :: "n"(N));
}

// ============================================================
//            pre-pass kernels (tf32 rounding)
// ============================================================
__global__ __launch_bounds__(256) void round_copy_kernel(
    const float* __restrict__ src, float* __restrict__ dst)
{
    int i = blockIdx.x * 256 + threadIdx.x;
    float4 v = ((const float4*)src)[i];
    v.x = f2tf32f(v.x); v.y = f2tf32f(v.y);
    v.z = f2tf32f(v.z); v.w = f2tf32f(v.w);
    ((float4*)dst)[i] = v;
}

// dst[N][K] = round(src[K][N]); tiled transpose
__global__ __launch_bounds__(256) void transpose_round_kernel(
    const float* __restrict__ src, float* __restrict__ dst, int K, int N)
{
    __shared__ float tile[32][33];
    const int n0 = blockIdx.x * 32;
    const int k0 = blockIdx.y * 32;
    const int tx = threadIdx.x & 31;
    const int ty = threadIdx.x >> 5;      // 0..7
    #pragma unroll
    for (int i = 0; i < 4; i++)
        tile[ty + 8 * i][tx] = src[(size_t)(k0 + ty + 8 * i) * N + n0 + tx];
    __syncthreads();
    #pragma unroll
    for (int i = 0; i < 4; i++)
        dst[(size_t)(n0 + ty + 8 * i) * K + k0 + tx] = f2tf32f(tile[tx][ty + 8 * i]);
}

// ============================================================
//    TF32 GEMM: CTA 128x256x32, 8 warps, warp tile 64x64
//    3-stage cp.async pipeline + ldmatrix. Inputs pre-rounded.
//  C[M,N] = A[M,K] @ Bt[N,K]^T.
// ============================================================
#define GBM 128
#define GBN 256
#define GBK 32
#define AS_STRIDE 36
#define A_TILE_WORDS (GBM * AS_STRIDE)              // 4608
#define B_TILE_WORDS (GBN * AS_STRIDE)              // 9216
#define STAGE_WORDS  (A_TILE_WORDS + B_TILE_WORDS)  // 13824
#define NSTAGE 3
#define GEMM_SMEM_BYTES (NSTAGE * STAGE_WORDS * 4)  // 165888
#define RSTEP ((32 * AS_STRIDE) << 2)

__global__ __launch_bounds__(256, 1) void tf32_gemm_kernel(
    const float* __restrict__ A, const float* __restrict__ Bt,
    float* __restrict__ C, int M, int N, int K)
{
    extern __shared__ uint32_t smg[];

    const int tid  = threadIdx.x;
    const int lane = tid & 31;
    const int wid  = tid >> 5;
    const int g    = lane >> 2;
    const int tg   = lane & 3;
    const int wm   = (wid & 1) * 64;      // 2 m positions
    const int wn   = (wid >> 1) * 64;     // 4 n positions

    const int bm = blockIdx.y * GBM;
    const int bn = blockIdx.x * GBN;

    // loader mapping: 16B chunk per thread, rows step by 32
    const int r0 = tid >> 3;            // 0..31
    const int cg = (tid & 7) * 4;       // 0..28
    const float* Ap[4];
    const float* Bp[8];
    #pragma unroll
    for (int i = 0; i < 4; i++)
        Ap[i] = A  + (size_t)(bm + r0 + 32 * i) * K + cg;
    #pragma unroll
    for (int i = 0; i < 8; i++)
        Bp[i] = Bt + (size_t)(bn + r0 + 32 * i) * K + cg;

    const uint32_t sm_base = (uint32_t)__cvta_generic_to_shared(smg);
    const uint32_t adst = sm_base + ((r0 * AS_STRIDE + cg) << 2);
    const uint32_t bdst = sm_base + ((A_TILE_WORDS + r0 * AS_STRIDE + cg) << 2);

    // per-lane ldmatrix addresses (stage 0)
    const int r7  = lane & 7;
    const int r8  = (lane >> 3) & 1;
    const int r16 = lane >> 4;
    uint32_t aaddr[4], baddr[4];
    #pragma unroll
    for (int mt = 0; mt < 4; mt++)
        aaddr[mt] = sm_base + (((wm + mt * 16 + r8 * 8 + r7) * AS_STRIDE + r16 * 4) << 2);
    #pragma unroll
    for (int ntp = 0; ntp < 4; ntp++)
        baddr[ntp] = sm_base + ((A_TILE_WORDS + (wn + ntp * 16 + r16 * 8 + r7) * AS_STRIDE + r8 * 4) << 2);

    const int nk = K / GBK;

    // prologue: stages 0,1
    #pragma unroll
    for (int s = 0; s < 2; s++) {
        uint32_t so = s * (STAGE_WORDS << 2);
        #pragma unroll
        for (int i = 0; i < 4; i++)
            cp16(adst + so + i * RSTEP, Ap[i] + s * GBK);
        #pragma unroll
        for (int i = 0; i < 8; i++)
            cp16(bdst + so + i * RSTEP, Bp[i] + s * GBK);
        cp_commit();
    }

    float acc[4][8][4];
    #pragma unroll
    for (int mt = 0; mt < 4; mt++)
        #pragma unroll
        for (int nt = 0; nt < 8; nt++)
            #pragma unroll
            for (int e = 0; e < 4; e++) acc[mt][nt][e] = 0.f;

    for (int kt = 0; kt < nk; kt++) {
        cp_wait<1>();
        __syncthreads();

        // issue stage kt+2
        if (kt + 2 < nk) {
            uint32_t so = ((kt + 2) % NSTAGE) * (STAGE_WORDS << 2);
            int ko = (kt + 2) * GBK;
            #pragma unroll
            for (int i = 0; i < 4; i++)
                cp16(adst + so + i * RSTEP, Ap[i] + ko);
            #pragma unroll
            for (int i = 0; i < 8; i++)
                cp16(bdst + so + i * RSTEP, Bp[i] + ko);
        }
        cp_commit();

        // compute stage kt
        const uint32_t so = (kt % NSTAGE) * (STAGE_WORDS << 2);
        #pragma unroll
        for (int kc = 0; kc < 4; kc++) {
            uint32_t af[4][4];
            uint32_t bf[4][4];
            #pragma unroll
            for (int mt = 0; mt < 4; mt++)
                ldmx4(af[mt], aaddr[mt] + so + kc * 32);
            #pragma unroll
            for (int ntp = 0; ntp < 4; ntp++)
                ldmx4(bf[ntp], baddr[ntp] + so + kc * 32);
            #pragma unroll
            for (int mt = 0; mt < 4; mt++)
                #pragma unroll
                for (int ntp = 0; ntp < 4; ntp++) {
                    mma_tf32(acc[mt][2 * ntp],     af[mt], bf[ntp]);
                    mma_tf32(acc[mt][2 * ntp + 1], af[mt], bf[ntp] + 2);
                }
        }
    }

    // epilogue
    #pragma unroll
    for (int mt = 0; mt < 4; mt++) {
        int r = bm + wm + mt * 16 + g;
        #pragma unroll
        for (int nt = 0; nt < 8; nt++) {
            int c0 = bn + wn + nt * 8 + tg * 2;
            *(float2*)(C + (size_t)r * N + c0)       = make_float2(acc[mt][nt][0], acc[mt][nt][1]);
            *(float2*)(C + (size_t)(r + 8) * N + c0) = make_float2(acc[mt][nt][2], acc[mt][nt][3]);
        }
    }
}

// ============================ RoPE + split ============================
// Q/K/V outputs rounded to tf32. V stored TRANSPOSED: g_v[b,kvh][d][s]
__global__ __launch_bounds__(256) void rope_split_kernel(
    const float* __restrict__ qkv,
    float* __restrict__ Qb, float* __restrict__ Kb, float* __restrict__ Vb)
{
    const int m = blockIdx.x;
    const int b = m >> 11;
    const int s = m & 2047;
    const int tid = threadIdx.x;

    __shared__ float cosr[48], sinr[48];
    if (tid < 48) {
        float invf = powf(10000.f, -((float)(2 * tid)) / 96.f);
        float ang  = (float)s * invf;
        cosr[tid] = cosf(ang);
        sinr[tid] = sinf(ang);
    }
    __syncthreads();

    const float* row = qkv + (size_t)m * OPSZ;

    for (int idx = tid; idx < (NH + NKV) * 48; idx += 256) {
        int hh = idx / 48;
        int j  = idx % 48;
        float c  = cosr[j];
        float sn = sinr[j];
        if (hh < NH) {
            float x1 = row[hh * HD + j];
            float x2 = row[hh * HD + j + 48];
            size_t base = ((size_t)(b * NH + hh)) * SEQ * HD + (size_t)s * HD;
            Qb[base + j]      = f2tf32f((x1 * c - x2 * sn) * QK_SCALE);
            Qb[base + j + 48] = f2tf32f((x2 * c + x1 * sn) * QK_SCALE);
        } else {
            int kh = hh - NH;
            float x1 = row[NH * HD + kh * HD + j];
            float x2 = row[NH * HD + kh * HD + j + 48];
            size_t base = ((size_t)(b * NKV + kh)) * SEQ * HD + (size_t)s * HD;
            Kb[base + j]      = f2tf32f(x1 * c - x2 * sn);
            Kb[base + j + 48] = f2tf32f(x2 * c + x1 * sn);
        }
    }
    for (int idx = tid; idx < NKV * HD; idx += 256) {
        int kh = idx / HD, d = idx % HD;
        Vb[((size_t)(b * NKV + kh) * HD + d) * SEQ + s] =
            f2tf32f(row[NH * HD + NKV * HD + idx]);
    }
}

// ============================================================
//   Tensor-core flash attention: BQ=128, 512 threads, 16 warps
//  QK warps 8m x 2n (16x32); PV 8m x 2n (16x48). cp.async staging.
// ============================================================
#define AT_BQ 128
#define AT_BK 64
#define QK_STRIDE 100   // words; conflict-free ldmatrix
#define VT_STRIDE 68
#define P_STRIDE  68

#define ATTN_SMEM_U32 (AT_BQ*QK_STRIDE + AT_BK*QK_STRIDE + HD*VT_STRIDE + AT_BQ*P_STRIDE + 3*AT_BQ)
#define ATTN_SMEM_BYTES (ATTN_SMEM_U32 * 4)   // 139264

__global__ __launch_bounds__(512, 1) void attn_tc_kernel(
    const float* __restrict__ Q, const float* __restrict__ K,
    const float* __restrict__ V, float* __restrict__ O)
{
    extern __shared__ uint32_t smu[];
    uint32_t* q_s = smu;                              // [128][100]
    uint32_t* k_s = q_s + AT_BQ * QK_STRIDE;          // [64][100] ([n][k] for QK B)
    uint32_t* vt_s = k_s + AT_BK * QK_STRIDE;         // [96][68]  ([n][k] for PV B)
    float*    p_s = (float*)(vt_s + HD * VT_STRIDE);  // [128][68]
    float*    m_s = p_s + AT_BQ * P_STRIDE;
    float*    l_s = m_s + AT_BQ;
    float*    al_s = l_s + AT_BQ;

    const int tid  = threadIdx.x;
    const int lane = tid & 31;
    const int wid  = tid >> 5;           // 0..15
    const int g    = lane >> 2;
    const int tg   = lane & 3;
    const int wm   = (wid & 7) * 16;     // 8 m positions
    const int wn   = (wid >> 3) * 32;    // 2 n positions (QK)
    const int wnp  = (wid >> 3) * 48;    // 2 n positions (PV)

    const int tileq = (gridDim.x - 1) - blockIdx.x;   // heavy CTAs first
    const int bh = blockIdx.y;
    const int b  = bh >> 5;
    const int h  = bh & 31;
    const int kvh = h >> 2;
    const int q0 = tileq * AT_BQ;

    const float* Qb = Q + (size_t)bh * SEQ * HD;
    const float* Kb = K + (size_t)(b * NKV + kvh) * SEQ * HD;
    const float* Vb = V + (size_t)(b * NKV + kvh) * HD * SEQ;  // [d][s]

    const uint32_t q_base = (uint32_t)__cvta_generic_to_shared(q_s);
    const uint32_t k_base = (uint32_t)__cvta_generic_to_shared(k_s);
    const uint32_t v_base = (uint32_t)__cvta_generic_to_shared(vt_s);
    const uint32_t p_base = (uint32_t)__cvta_generic_to_shared(p_s);

    // per-lane ldmatrix addresses
    const int r7  = lane & 7;
    const int r8  = (lane >> 3) & 1;
    const int r16 = lane >> 4;
    uint32_t qaddr = q_base + (((wm + r8 * 8 + r7) * QK_STRIDE + r16 * 4) << 2);
    uint32_t paddr = p_base + (((wm + r8 * 8 + r7) * P_STRIDE + r16 * 4) << 2);
    uint32_t kaddr[2], vaddr[3];
    #pragma unroll
    for (int ntp = 0; ntp < 2; ntp++)
        kaddr[ntp] = k_base + (((wn + ntp * 16 + r16 * 8 + r7) * QK_STRIDE + r8 * 4) << 2);
    #pragma unroll
    for (int ntp = 0; ntp < 3; ntp++)
        vaddr[ntp] = v_base + (((wnp + ntp * 16 + r16 * 8 + r7) * VT_STRIDE + r8 * 4) << 2);

    // ---- prologue: cp.async Q tile (128 rows) + K tile 0 ----
    #pragma unroll
    for (int i = 0; i < 6; i++) {
        int f = tid + 512 * i;          // < 3072
        int row = f / 24;
        int c4  = (f % 24) * 4;
        cp16(q_base + ((row * QK_STRIDE + c4) << 2),
             Qb + (size_t)(q0 + row) * HD + c4);
    }
    #pragma unroll
    for (int i = 0; i < 3; i++) {
        int f = tid + 512 * i;          // < 1536
        int row = f / 24;
        int c4  = (f % 24) * 4;
        cp16(k_base + ((row * QK_STRIDE + c4) << 2),
             Kb + (size_t)row * HD + c4);
    }
    cp_commit();

    if (tid < AT_BQ) { m_s[tid] = -1e30f; l_s[tid] = 0.f; }

    float acc[6][4];
    #pragma unroll
    for (int nt = 0; nt < 6; nt++)
        #pragma unroll
        for (int e = 0; e < 4; e++) acc[nt][e] = 0.f;

    const int ntiles = 2 * (tileq + 1);
    for (int t = 0; t < ntiles; t++) {
        const int k0 = t * AT_BK;
        __syncthreads();       // prev iter fully done (v_s, p_s free)

        // issue V_t
        #pragma unroll
        for (int i = 0; i < 3; i++) {
            int f = tid + 512 * i;      // < 1536
            int d = f >> 4;
            int j4 = (f & 15) * 4;
            cp16(v_base + ((d * VT_STRIDE + j4) << 2),
                 Vb + (size_t)d * SEQ + k0 + j4);
        }
        cp_commit();
        cp_wait<0>();          // Q + K_t + V_t all arrived
        __syncthreads();

        // ---- S = Q K^T via MMA: K=96 ----
        float s4[4][4];
        #pragma unroll
        for (int nt = 0; nt < 4; nt++)
            #pragma unroll
            for (int e = 0; e < 4; e++) s4[nt][e] = 0.f;

        #pragma unroll
        for (int kc = 0; kc < 12; kc++) {
            uint32_t a[4];
            ldmx4(a, qaddr + kc * 32);
            #pragma unroll
            for (int ntp = 0; ntp < 2; ntp++) {
                uint32_t bf[4];
                ldmx4(bf, kaddr[ntp] + kc * 32);
                mma_tf32(s4[2 * ntp],     a, bf);
                mma_tf32(s4[2 * ntp + 1], a, bf + 2);
            }
        }

        // ---- mask (tiles overlapping diagonal) + store scores ----
        const bool diag = (t >= 2 * tileq);
        const int row0 = q0 + wm + g;
        #pragma unroll
        for (int nt = 0; nt < 4; nt++) {
            int col = k0 + wn + nt * 8 + 2 * tg;
            float v0 = s4[nt][0], v1 = s4[nt][1];
            float v2 = s4[nt][2], v3 = s4[nt][3];
            if (diag) {
                if (col     > row0)     v0 = -1e30f;
                if (col + 1 > row0)     v1 = -1e30f;
                if (col     > row0 + 8) v2 = -1e30f;
                if (col + 1 > row0 + 8) v3 = -1e30f;
            }
            int c = wn + nt * 8 + 2 * tg;
            *(float2*)&p_s[(wm + g) * P_STRIDE + c]     = make_float2(v0, v1);
            *(float2*)&p_s[(wm + g + 8) * P_STRIDE + c] = make_float2(v2, v3);
        }
        __syncthreads();       // QK done -> k_s free; p_s visible

        // prefetch K_{t+1}, overlapped with softmax + PV
        if (t + 1 < ntiles) {
            const int k0n = k0 + AT_BK;
            #pragma unroll
            for (int i = 0; i < 3; i++) {
                int f = tid + 512 * i;
                int row = f / 24;
                int c4  = (f % 24) * 4;
                cp16(k_base + ((row * QK_STRIDE + c4) << 2),
                     Kb + (size_t)(k0n + row) * HD + c4);
            }
        }
        cp_commit();

        // ---- online softmax: 4 threads per row (512 thr, 128 rows) ----
        {
            const int r  = tid >> 2;
            const int qt = tid & 3;
            float* prow = &p_s[r * P_STRIDE + qt * 16];
            float mold = m_s[r];
            float mt = mold;
            #pragma unroll
            for (int j = 0; j < 16; j++) mt = fmaxf(mt, prow[j]);
            mt = fmaxf(mt, __shfl_xor_sync(0xffffffffu, mt, 1));
            mt = fmaxf(mt, __shfl_xor_sync(0xffffffffu, mt, 2));
            float alpha = __expf(mold - mt);
            float sum = 0.f;
            #pragma unroll
            for (int j = 0; j < 16; j++) {
                float e = __expf(prow[j] - mt);
                sum += e;
                prow[j] = __uint_as_float(f2tf32(e));
            }
            sum += __shfl_xor_sync(0xffffffffu, sum, 1);
            sum += __shfl_xor_sync(0xffffffffu, sum, 2);
            if (qt == 0) {
                m_s[r]  = mt;
                l_s[r]  = l_s[r] * alpha + sum;
                al_s[r] = alpha;
            }
        }
        __syncthreads();

        // ---- rescale O accumulators ----
        {
            float a0 = al_s[wm + g];
            float a1 = al_s[wm + g + 8];
            #pragma unroll
            for (int nt = 0; nt < 6; nt++) {
                acc[nt][0] *= a0; acc[nt][1] *= a0;
                acc[nt][2] *= a1; acc[nt][3] *= a1;
            }
        }

        // ---- O += P V via MMA: K=64 ----
        #pragma unroll
        for (int kc = 0; kc < 8; kc++) {
            uint32_t a[4];
            ldmx4(a, paddr + kc * 32);
            #pragma unroll
            for (int ntp = 0; ntp < 3; ntp++) {
                uint32_t bf[4];
                ldmx4(bf, vaddr[ntp] + kc * 32);
                mma_tf32(acc[2 * ntp],     a, bf);
                mma_tf32(acc[2 * ntp + 1], a, bf + 2);
            }
        }
    }

    // ---- epilogue: normalize, round to tf32 (O-proj A operand), write ----
    {
        const int r0 = wm + g;
        const float inv0 = 1.f / l_s[r0];
        const float inv1 = 1.f / l_s[r0 + 8];
        size_t base0 = ((size_t)(b * SEQ + q0 + r0)) * HID + h * HD;
        size_t base1 = base0 + 8 * HID;
        #pragma unroll
        for (int nt = 0; nt < 6; nt++) {
            int c = wnp + nt * 8 + 2 * tg;
            *(float2*)(O + base0 + c) =
                make_float2(f2tf32f(acc[nt][0] * inv0), f2tf32f(acc[nt][1] * inv0));
            *(float2*)(O + base1 + c) =
                make_float2(f2tf32f(acc[nt][2] * inv1), f2tf32f(acc[nt][3] * inv1));
        }
    }
}

// ============================ launch ============================
extern "C" void kernel_launch(void* const* d_in, const int* in_sizes, int n_in,
                              void* d_out, int out_size)
{
    const float* hs   = (const float*)d_in[0];   // hidden_states
    // d_in[1] = position_ids (arange, unused)
    // d_in[2] = attention_mask (causal, unused)
    const float* Wqkv = (const float*)d_in[3];
    const float* Wo   = (const float*)d_in[4];
    float* out = (float*)d_out;

    float *qkv, *Qb, *Kb, *Vb, *att, *hs_r, *wqkvt, *wot;
    cudaGetSymbolAddress((void**)&qkv,   g_qkv);
    cudaGetSymbolAddress((void**)&Qb,    g_q);
    cudaGetSymbolAddress((void**)&Kb,    g_k);
    cudaGetSymbolAddress((void**)&Vb,    g_v);
    cudaGetSymbolAddress((void**)&att,   g_att);
    cudaGetSymbolAddress((void**)&hs_r,  g_hs_r);
    cudaGetSymbolAddress((void**)&wqkvt, g_wqkvt);
    cudaGetSymbolAddress((void**)&wot,   g_wot);

    cudaFuncSetAttribute(tf32_gemm_kernel,
                         cudaFuncAttributeMaxDynamicSharedMemorySize,
                         GEMM_SMEM_BYTES);
    cudaFuncSetAttribute(attn_tc_kernel,
                         cudaFuncAttributeMaxDynamicSharedMemorySize,
                         ATTN_SMEM_BYTES);

    // 0) pre-round hidden_states; pre-round+transpose weights
    round_copy_kernel<<<(MROWS * HID / 4) / 256, 256>>>(hs, hs_r);
    transpose_round_kernel<<<dim3(OPSZ / 32, HID / 32), 256>>>(Wqkv, wqkvt, HID, OPSZ);
    transpose_round_kernel<<<dim3(HID / 32, HID / 32), 256>>>(Wo, wot, HID, HID);

    // 1) QKV projection (128x256 tile, cp.async pipeline)
    tf32_gemm_kernel<<<dim3(OPSZ / GBN, MROWS / GBM), 256, GEMM_SMEM_BYTES>>>(
        hs_r, wqkvt, qkv, MROWS, OPSZ, HID);

    // 2) RoPE + split (rounded; V transposed to [d][s])
    rope_split_kernel<<<MROWS, 256>>>(qkv, Qb, Kb, Vb);

    // 3) causal GQA flash attention (BQ=128, 512 threads)
    attn_tc_kernel<<<dim3(SEQ / AT_BQ, BATCH * NH), 512, ATTN_SMEM_BYTES>>>(
        Qb, Kb, Vb, att);

    // 4) output projection
    tf32_gemm_kernel<<<dim3(HID / GBN, MROWS / GBM), 256, GEMM_SMEM_BYTES>>>(
        att, wot, out, MROWS, HID, HID);
}

// round 8
// speedup vs baseline: 1.0705x; 1.0705x over previous
#include <cuda_runtime.h>
#include <cuda_bf16.h>
#include <math.h>
#include <stdint.h>

// Problem constants
#define BATCH   2
#define SEQ     2048
#define HID     3072
#define NH      32
#define NKV     8
#define HD      96
#define OPSZ    4608          // NH*HD + 2*NKV*HD
#define MROWS   4096          // BATCH*SEQ
#define QK_SCALE 0.10206207261596577f  // 1/sqrt(96)

// ---------------- scratch (device globals, no allocation) ----------------
__device__ float g_qkv  [(size_t)MROWS * OPSZ];
__device__ float g_q    [(size_t)BATCH * NH  * SEQ * HD];
__device__ float g_k    [(size_t)BATCH * NKV * SEQ * HD];
__device__ float g_v    [(size_t)BATCH * NKV * SEQ * HD];  // TRANSPOSED: [b,kvh][d][s]
__device__ float g_att  [(size_t)MROWS * HID];
__device__ float g_hs_r [(size_t)MROWS * HID];             // tf32-rounded hidden_states
__device__ float g_wqkvt[(size_t)OPSZ * HID];              // Wqkv^T [n][k], tf32-rounded
__device__ float g_wot  [(size_t)HID * HID];               // Wo^T   [n][k], tf32-rounded

// ============================================================
//          TF32 MMA + ldmatrix + cp.async helpers
// ============================================================
__device__ __forceinline__ uint32_t f2tf32(float x) {
    uint32_t r;
    asm("cvt.rna.tf32.f32 %0, %1;" : "=r"(r) : "f"(x));
    return r;
}
__device__ __forceinline__ float f2tf32f(float x) {
    return __uint_as_float(f2tf32(x));
}

__device__ __forceinline__ void mma_tf32(float* c, const uint32_t* a, const uint32_t* b) {
    asm volatile(
        "mma.sync.aligned.m16n8k8.row.col.f32.tf32.tf32.f32 "
        "{%0,%1,%2,%3}, {%4,%5,%6,%7}, {%8,%9}, {%0,%1,%2,%3};\n"
        : "+f"(c[0]), "+f"(c[1]), "+f"(c[2]), "+f"(c[3])
        : "r"(a[0]), "r"(a[1]), "r"(a[2]), "r"(a[3]),
          "r"(b[0]), "r"(b[1]));
}

__device__ __forceinline__ void ldmx4(uint32_t* r, uint32_t addr) {
    asm volatile("ldmatrix.sync.aligned.m8n8.x4.shared.b16 {%0,%1,%2,%3}, [%4];"
        : "=r"(r[0]), "=r"(r[1]), "=r"(r[2]), "=r"(r[3]) : "r"(addr));
}

__device__ __forceinline__ void cp16(uint32_t dst, const void* src) {
    asm volatile("cp.async.cg.shared.global [%0], [%1], 16;" :: "r"(dst), "l"(src));
}
__device__ __forceinline__ void cp_commit() {
    asm volatile("cp.async.commit_group;");
}
template<int N> __device__ __forceinline__ void cp_wait() {
    asm volatile("cp.async.wait_group %0;" :: "n"(N));
}

// ============================================================
//            pre-pass kernels (tf32 rounding)
// ============================================================
__global__ __launch_bounds__(256) void round_copy_kernel(
    const float* __restrict__ src, float* __restrict__ dst)
{
    int i = blockIdx.x * 256 + threadIdx.x;
    float4 v = ((const float4*)src)[i];
    v.x = f2tf32f(v.x); v.y = f2tf32f(v.y);
    v.z = f2tf32f(v.z); v.w = f2tf32f(v.w);
    ((float4*)dst)[i] = v;
}

// dst[N][K] = round(src[K][N]); tiled transpose
__global__ __launch_bounds__(256) void transpose_round_kernel(
    const float* __restrict__ src, float* __restrict__ dst, int K, int N)
{
    __shared__ float tile[32][33];
    const int n0 = blockIdx.x * 32;
    const int k0 = blockIdx.y * 32;
    const int tx = threadIdx.x & 31;
    const int ty = threadIdx.x >> 5;      // 0..7
    #pragma unroll
    for (int i = 0; i < 4; i++)
        tile[ty + 8 * i][tx] = src[(size_t)(k0 + ty + 8 * i) * N + n0 + tx];
    __syncthreads();
    #pragma unroll
    for (int i = 0; i < 4; i++)
        dst[(size_t)(n0 + ty + 8 * i) * K + k0 + tx] = f2tf32f(tile[tx][ty + 8 * i]);
}

// ============================================================
//    TF32 GEMM, 3-stage cp.async pipeline + ldmatrix
//  C[M,N] = A[M,K] @ Bt[N,K]^T. Inputs pre-rounded to tf32.
//  CTA 128x128x32, 8 warps (4m x 2n), warp tile 32x64.  (round-5 proven)
// ============================================================
#define GBM 128
#define GBN 128
#define GBK 32
#define AS_STRIDE 36
#define A_TILE_WORDS (GBM * AS_STRIDE)      // 4608
#define STAGE_WORDS  (2 * A_TILE_WORDS)     // 9216
#define NSTAGE 3
#define GEMM_SMEM_BYTES (NSTAGE * STAGE_WORDS * 4)   // 110592

__global__ __launch_bounds__(256, 2) void tf32_gemm_kernel(
    const float* __restrict__ A, const float* __restrict__ Bt,
    float* __restrict__ C, int M, int N, int K)
{
    extern __shared__ uint32_t smg[];

    const int tid  = threadIdx.x;
    const int lane = tid & 31;
    const int wid  = tid >> 5;
    const int g    = lane >> 2;
    const int tg   = lane & 3;
    const int wm   = (wid & 3) * 32;
    const int wn   = (wid >> 2) * 64;

    const int bm = blockIdx.y * GBM;
    const int bn = blockIdx.x * GBN;

    // loader mapping: thread covers rows r0+32i, fixed 4-word col group
    const int r0 = tid >> 3;            // 0..31
    const int cg = (tid & 7) * 4;       // 0..28
    const float* Ap[4];
    const float* Bp[4];
    #pragma unroll
    for (int i = 0; i < 4; i++) {
        Ap[i] = A  + (size_t)(bm + r0 + 32 * i) * K + cg;
        Bp[i] = Bt + (size_t)(bn + r0 + 32 * i) * K + cg;
    }
    const uint32_t sm_base = (uint32_t)__cvta_generic_to_shared(smg);
    const uint32_t adst = sm_base + ((r0 * AS_STRIDE + cg) << 2);
    const uint32_t bdst = adst + (A_TILE_WORDS << 2);

    // per-lane ldmatrix addresses (within stage 0)
    const int r7  = lane & 7;
    const int r8  = (lane >> 3) & 1;
    const int r16 = lane >> 4;
    uint32_t aaddr[2], baddr[4];
    #pragma unroll
    for (int mt = 0; mt < 2; mt++)
        aaddr[mt] = sm_base + (((wm + mt * 16 + r8 * 8 + r7) * AS_STRIDE + r16 * 4) << 2);
    #pragma unroll
    for (int ntp = 0; ntp < 4; ntp++)
        baddr[ntp] = sm_base + ((A_TILE_WORDS + (wn + ntp * 16 + r16 * 8 + r7) * AS_STRIDE + r8 * 4) << 2);

    const int nk = K / GBK;

    // prologue: stages 0,1
    #pragma unroll
    for (int s = 0; s < 2; s++) {
        uint32_t so = s * (STAGE_WORDS << 2);
        #pragma unroll
        for (int i = 0; i < 4; i++) {
            cp16(adst + so + i * ((32 * AS_STRIDE) << 2), Ap[i] + s * GBK);
            cp16(bdst + so + i * ((32 * AS_STRIDE) << 2), Bp[i] + s * GBK);
        }
        cp_commit();
    }

    float acc[2][8][4];
    #pragma unroll
    for (int mt = 0; mt < 2; mt++)
        #pragma unroll
        for (int nt = 0; nt < 8; nt++)
            #pragma unroll
            for (int e = 0; e < 4; e++) acc[mt][nt][e] = 0.f;

    for (int kt = 0; kt < nk; kt++) {
        cp_wait<1>();
        __syncthreads();

        // issue stage kt+2 (buffer free: computed at iter kt-1)
        if (kt + 2 < nk) {
            uint32_t so = ((kt + 2) % NSTAGE) * (STAGE_WORDS << 2);
            int ko = (kt + 2) * GBK;
            #pragma unroll
            for (int i = 0; i < 4; i++) {
                cp16(adst + so + i * ((32 * AS_STRIDE) << 2), Ap[i] + ko);
                cp16(bdst + so + i * ((32 * AS_STRIDE) << 2), Bp[i] + ko);
            }
        }
        cp_commit();

        // compute stage kt
        const uint32_t so = (kt % NSTAGE) * (STAGE_WORDS << 2);
        #pragma unroll
        for (int kc = 0; kc < 4; kc++) {
            uint32_t af[2][4];
            ldmx4(af[0], aaddr[0] + so + kc * 32);
            ldmx4(af[1], aaddr[1] + so + kc * 32);
            #pragma unroll
            for (int ntp = 0; ntp < 4; ntp++) {
                uint32_t bf[4];
                ldmx4(bf, baddr[ntp] + so + kc * 32);
                mma_tf32(acc[0][2 * ntp],     af[0], bf);
                mma_tf32(acc[0][2 * ntp + 1], af[0], bf + 2);
                mma_tf32(acc[1][2 * ntp],     af[1], bf);
                mma_tf32(acc[1][2 * ntp + 1], af[1], bf + 2);
            }
        }
    }

    // epilogue
    #pragma unroll
    for (int mt = 0; mt < 2; mt++) {
        int r = bm + wm + mt * 16 + g;
        #pragma unroll
        for (int nt = 0; nt < 8; nt++) {
            int c0 = bn + wn + nt * 8 + tg * 2;
            *(float2*)(C + (size_t)r * N + c0)       = make_float2(acc[mt][nt][0], acc[mt][nt][1]);
            *(float2*)(C + (size_t)(r + 8) * N + c0) = make_float2(acc[mt][nt][2], acc[mt][nt][3]);
        }
    }
}

// ============================ RoPE + split ============================
// Q/K/V outputs rounded to tf32. V stored TRANSPOSED: g_v[b,kvh][d][s]
__global__ __launch_bounds__(256) void rope_split_kernel(
    const float* __restrict__ qkv,
    float* __restrict__ Qb, float* __restrict__ Kb, float* __restrict__ Vb)
{
    const int m = blockIdx.x;
    const int b = m >> 11;
    const int s = m & 2047;
    const int tid = threadIdx.x;

    __shared__ float cosr[48], sinr[48];
    if (tid < 48) {
        float invf = powf(10000.f, -((float)(2 * tid)) / 96.f);
        float ang  = (float)s * invf;
        cosr[tid] = cosf(ang);
        sinr[tid] = sinf(ang);
    }
    __syncthreads();

    const float* row = qkv + (size_t)m * OPSZ;

    for (int idx = tid; idx < (NH + NKV) * 48; idx += 256) {
        int hh = idx / 48;
        int j  = idx % 48;
        float c  = cosr[j];
        float sn = sinr[j];
        if (hh < NH) {
            float x1 = row[hh * HD + j];
            float x2 = row[hh * HD + j + 48];
            size_t base = ((size_t)(b * NH + hh)) * SEQ * HD + (size_t)s * HD;
            Qb[base + j]      = f2tf32f((x1 * c - x2 * sn) * QK_SCALE);
            Qb[base + j + 48] = f2tf32f((x2 * c + x1 * sn) * QK_SCALE);
        } else {
            int kh = hh - NH;
            float x1 = row[NH * HD + kh * HD + j];
            float x2 = row[NH * HD + kh * HD + j + 48];
            size_t base = ((size_t)(b * NKV + kh)) * SEQ * HD + (size_t)s * HD;
            Kb[base + j]      = f2tf32f(x1 * c - x2 * sn);
            Kb[base + j + 48] = f2tf32f(x2 * c + x1 * sn);
        }
    }
    for (int idx = tid; idx < NKV * HD; idx += 256) {
        int kh = idx / HD, d = idx % HD;
        Vb[((size_t)(b * NKV + kh) * HD + d) * SEQ + s] =
            f2tf32f(row[NH * HD + NKV * HD + idx]);
    }
}

// ============================================================
//   Tensor-core flash attention (tf32 + ldmatrix + cp.async)
//  CTA = (64 q-rows, b*NH+h). 256 threads, 8 warps. 2 CTAs/SM.
//  V latency hidden: wait only K before QK, wait V after softmax.
// ============================================================
#define AT_BQ 64
#define AT_BK 64
#define QK_STRIDE 100   // words; conflict-free ldmatrix
#define VT_STRIDE 68
#define P_STRIDE  68

#define ATTN_SMEM_U32 (AT_BQ*QK_STRIDE + AT_BK*QK_STRIDE + HD*VT_STRIDE + AT_BQ*P_STRIDE + 3*AT_BQ)
#define ATTN_SMEM_BYTES (ATTN_SMEM_U32 * 4)

__global__ __launch_bounds__(256, 2) void attn_tc_kernel(
    const float* __restrict__ Q, const float* __restrict__ K,
    const float* __restrict__ V, float* __restrict__ O)
{
    extern __shared__ uint32_t smu[];
    uint32_t* q_s = smu;                              // [64][100]
    uint32_t* k_s = q_s + AT_BQ * QK_STRIDE;          // [64][100] ([n][k] for QK B)
    uint32_t* vt_s = k_s + AT_BK * QK_STRIDE;         // [96][68]  ([n][k] for PV B)
    float*    p_s = (float*)(vt_s + HD * VT_STRIDE);  // [64][68]
    float*    m_s = p_s + AT_BQ * P_STRIDE;
    float*    l_s = m_s + AT_BQ;
    float*    al_s = l_s + AT_BQ;

    const int tid  = threadIdx.x;
    const int lane = tid & 31;
    const int wid  = tid >> 5;
    const int g    = lane >> 2;
    const int tg   = lane & 3;
    const int wm   = (wid & 3) * 16;
    const int wn   = (wid >> 2) * 32;
    const int wnp  = (wid >> 2) * 48;

    const int tileq = (gridDim.x - 1) - blockIdx.x;   // heavy causal CTAs first
    const int bh = blockIdx.y;
    const int b  = bh >> 5;
    const int h  = bh & 31;
    const int kvh = h >> 2;
    const int q0 = tileq * AT_BQ;

    const float* Qb = Q + (size_t)bh * SEQ * HD;
    const float* Kb = K + (size_t)(b * NKV + kvh) * SEQ * HD;
    const float* Vb = V + (size_t)(b * NKV + kvh) * HD * SEQ;  // [d][s]

    const uint32_t q_base = (uint32_t)__cvta_generic_to_shared(q_s);
    const uint32_t k_base = (uint32_t)__cvta_generic_to_shared(k_s);
    const uint32_t v_base = (uint32_t)__cvta_generic_to_shared(vt_s);
    const uint32_t p_base = (uint32_t)__cvta_generic_to_shared(p_s);

    // per-lane ldmatrix addresses
    const int r7  = lane & 7;
    const int r8  = (lane >> 3) & 1;
    const int r16 = lane >> 4;
    uint32_t qaddr = q_base + (((wm + r8 * 8 + r7) * QK_STRIDE + r16 * 4) << 2);
    uint32_t paddr = p_base + (((wm + r8 * 8 + r7) * P_STRIDE + r16 * 4) << 2);
    uint32_t kaddr[2], vaddr[3];
    #pragma unroll
    for (int ntp = 0; ntp < 2; ntp++)
        kaddr[ntp] = k_base + (((wn + ntp * 16 + r16 * 8 + r7) * QK_STRIDE + r8 * 4) << 2);
    #pragma unroll
    for (int ntp = 0; ntp < 3; ntp++)
        vaddr[ntp] = v_base + (((wnp + ntp * 16 + r16 * 8 + r7) * VT_STRIDE + r8 * 4) << 2);

    // ---- prologue: cp.async Q tile + K tile 0 (one group) ----
    #pragma unroll
    for (int i = 0; i < 6; i++) {
        int f = tid + 256 * i;          // < 1536
        int row = f / 24;
        int c4  = (f % 24) * 4;
        cp16(q_base + ((row * QK_STRIDE + c4) << 2),
             Qb + (size_t)(q0 + row) * HD + c4);
        cp16(k_base + ((row * QK_STRIDE + c4) << 2),
             Kb + (size_t)row * HD + c4);
    }
    cp_commit();

    if (tid < AT_BQ) { m_s[tid] = -1e30f; l_s[tid] = 0.f; }

    float acc[6][4];
    #pragma unroll
    for (int nt = 0; nt < 6; nt++)
        #pragma unroll
        for (int e = 0; e < 4; e++) acc[nt][e] = 0.f;

    const int ntiles = tileq + 1;
    for (int t = 0; t < ntiles; t++) {
        const int k0 = t * AT_BK;
        __syncthreads();       // prev iter fully done (v_s, p_s free)

        // issue V_t (group); do NOT wait on it yet
        #pragma unroll
        for (int i = 0; i < 6; i++) {
            int f = tid + 256 * i;
            int d = f >> 4;
            int j4 = (f & 15) * 4;
            cp16(v_base + ((d * VT_STRIDE + j4) << 2),
                 Vb + (size_t)d * SEQ + k0 + j4);
        }
        cp_commit();

        cp_wait<1>();          // K_t (and Q) arrived; V_t may still be in flight
        __syncthreads();

        // ---- S = Q K^T via MMA: K=96 ----
        float s4[4][4];
        #pragma unroll
        for (int nt = 0; nt < 4; nt++)
            #pragma unroll
            for (int e = 0; e < 4; e++) s4[nt][e] = 0.f;

        #pragma unroll
        for (int kc = 0; kc < 12; kc++) {
            uint32_t a[4];
            ldmx4(a, qaddr + kc * 32);
            #pragma unroll
            for (int ntp = 0; ntp < 2; ntp++) {
                uint32_t bf[4];
                ldmx4(bf, kaddr[ntp] + kc * 32);
                mma_tf32(s4[2 * ntp],     a, bf);
                mma_tf32(s4[2 * ntp + 1], a, bf + 2);
            }
        }

        // ---- mask (diag tile) + store scores ----
        const bool diag = (t == tileq);
        const int row0 = q0 + wm + g;
        #pragma unroll
        for (int nt = 0; nt < 4; nt++) {
            int col = k0 + wn + nt * 8 + 2 * tg;
            float v0 = s4[nt][0], v1 = s4[nt][1];
            float v2 = s4[nt][2], v3 = s4[nt][3];
            if (diag) {
                if (col     > row0)     v0 = -1e30f;
                if (col + 1 > row0)     v1 = -1e30f;
                if (col     > row0 + 8) v2 = -1e30f;
                if (col + 1 > row0 + 8) v3 = -1e30f;
            }
            int c = wn + nt * 8 + 2 * tg;
            *(float2*)&p_s[(wm + g) * P_STRIDE + c]     = make_float2(v0, v1);
            *(float2*)&p_s[(wm + g + 8) * P_STRIDE + c] = make_float2(v2, v3);
        }
        __syncthreads();       // QK done -> k_s free; p_s visible

        // prefetch K_{t+1} into k_s, overlapped with softmax (+V in flight)
        if (t + 1 < ntiles) {
            const int k0n = k0 + AT_BK;
            #pragma unroll
            for (int i = 0; i < 6; i++) {
                int f = tid + 256 * i;
                int row = f / 24;
                int c4  = (f % 24) * 4;
                cp16(k_base + ((row * QK_STRIDE + c4) << 2),
                     Kb + (size_t)(k0n + row) * HD + c4);
            }
        }
        cp_commit();           // uniform group count even on last iter

        // ---- online softmax: 4 threads per row ----
        {
            const int r  = tid >> 2;
            const int qt = tid & 3;
            float* prow = &p_s[r * P_STRIDE + qt * 16];
            float mold = m_s[r];
            float mt = mold;
            #pragma unroll
            for (int j = 0; j < 16; j++) mt = fmaxf(mt, prow[j]);
            mt = fmaxf(mt, __shfl_xor_sync(0xffffffffu, mt, 1));
            mt = fmaxf(mt, __shfl_xor_sync(0xffffffffu, mt, 2));
            float alpha = __expf(mold - mt);
            float sum = 0.f;
            #pragma unroll
            for (int j = 0; j < 16; j++) {
                float e = __expf(prow[j] - mt);
                sum += e;
                prow[j] = __uint_as_float(f2tf32(e));
            }
            sum += __shfl_xor_sync(0xffffffffu, sum, 1);
            sum += __shfl_xor_sync(0xffffffffu, sum, 2);
            if (qt == 0) {
                m_s[r]  = mt;
                l_s[r]  = l_s[r] * alpha + sum;
                al_s[r] = alpha;
            }
        }

        cp_wait<1>();          // V_t arrived (K_{t+1} group may stay pending)
        __syncthreads();       // v_s visible to all; al_s visible

        // ---- rescale O accumulators ----
        {
            float a0 = al_s[wm + g];
            float a1 = al_s[wm + g + 8];
            #pragma unroll
            for (int nt = 0; nt < 6; nt++) {
                acc[nt][0] *= a0; acc[nt][1] *= a0;
                acc[nt][2] *= a1; acc[nt][3] *= a1;
            }
        }

        // ---- O += P V via MMA: K=64 ----
        #pragma unroll
        for (int kc = 0; kc < 8; kc++) {
            uint32_t a[4];
            ldmx4(a, paddr + kc * 32);
            #pragma unroll
            for (int ntp = 0; ntp < 3; ntp++) {
                uint32_t bf[4];
                ldmx4(bf, vaddr[ntp] + kc * 32);
                mma_tf32(acc[2 * ntp],     a, bf);
                mma_tf32(acc[2 * ntp + 1], a, bf + 2);
            }
        }
    }

    // ---- epilogue: normalize, round to tf32 (O-proj A operand), write ----
    {
        const int r0 = wm + g;
        const float inv0 = 1.f / l_s[r0];
        const float inv1 = 1.f / l_s[r0 + 8];
        size_t base0 = ((size_t)(b * SEQ + q0 + r0)) * HID + h * HD;
        size_t base1 = base0 + 8 * HID;
        #pragma unroll
        for (int nt = 0; nt < 6; nt++) {
            int c = wnp + nt * 8 + 2 * tg;
            *(float2*)(O + base0 + c) =
                make_float2(f2tf32f(acc[nt][0] * inv0), f2tf32f(acc[nt][1] * inv0));
            *(float2*)(O + base1 + c) =
                make_float2(f2tf32f(acc[nt][2] * inv1), f2tf32f(acc[nt][3] * inv1));
        }
    }
}

// ============================ launch ============================
extern "C" void kernel_launch(void* const* d_in, const int* in_sizes, int n_in,
                              void* d_out, int out_size)
{
    const float* hs   = (const float*)d_in[0];   // hidden_states
    // d_in[1] = position_ids (arange, unused)
    // d_in[2] = attention_mask (causal, unused)
    const float* Wqkv = (const float*)d_in[3];
    const float* Wo   = (const float*)d_in[4];
    float* out = (float*)d_out;

    float *qkv, *Qb, *Kb, *Vb, *att, *hs_r, *wqkvt, *wot;
    cudaGetSymbolAddress((void**)&qkv,   g_qkv);
    cudaGetSymbolAddress((void**)&Qb,    g_q);
    cudaGetSymbolAddress((void**)&Kb,    g_k);
    cudaGetSymbolAddress((void**)&Vb,    g_v);
    cudaGetSymbolAddress((void**)&att,   g_att);
    cudaGetSymbolAddress((void**)&hs_r,  g_hs_r);
    cudaGetSymbolAddress((void**)&wqkvt, g_wqkvt);
    cudaGetSymbolAddress((void**)&wot,   g_wot);

    cudaFuncSetAttribute(tf32_gemm_kernel,
                         cudaFuncAttributeMaxDynamicSharedMemorySize,
                         GEMM_SMEM_BYTES);
    cudaFuncSetAttribute(attn_tc_kernel,
                         cudaFuncAttributeMaxDynamicSharedMemorySize,
                         ATTN_SMEM_BYTES);

    // 0) pre-round hidden_states; pre-round+transpose weights
    round_copy_kernel<<<(MROWS * HID / 4) / 256, 256>>>(hs, hs_r);
    transpose_round_kernel<<<dim3(OPSZ / 32, HID / 32), 256>>>(Wqkv, wqkvt, HID, OPSZ);
    transpose_round_kernel<<<dim3(HID / 32, HID / 32), 256>>>(Wo, wot, HID, HID);

    // 1) QKV projection (cp.async 3-stage pipeline)
    tf32_gemm_kernel<<<dim3(OPSZ / GBN, MROWS / GBM), 256, GEMM_SMEM_BYTES>>>(
        hs_r, wqkvt, qkv, MROWS, OPSZ, HID);

    // 2) RoPE + split (rounded; V transposed to [d][s])
    rope_split_kernel<<<MROWS, 256>>>(qkv, Qb, Kb, Vb);

    // 3) causal GQA flash attention (V latency hidden)
    attn_tc_kernel<<<dim3(SEQ / AT_BQ, BATCH * NH), 256, ATTN_SMEM_BYTES>>>(
        Qb, Kb, Vb, att);

    // 4) output projection
    tf32_gemm_kernel<<<dim3(HID / GBN, MROWS / GBM), 256, GEMM_SMEM_BYTES>>>(
        att, wot, out, MROWS, HID, HID);
}

// round 13
// speedup vs baseline: 1.8508x; 1.7289x over previous
#include <cuda_runtime.h>
#include <cuda_fp16.h>
#include <math.h>
#include <stdint.h>

// Problem constants
#define BATCH   2
#define SEQ     2048
#define HID     3072
#define NH      32
#define NKV     8
#define HD      96
#define OPSZ    4608          // NH*HD + 2*NKV*HD
#define MROWS   4096          // BATCH*SEQ
#define QK_SCALE 0.10206207261596577f  // 1/sqrt(96)

// ---------------- scratch (device globals, no allocation) ----------------
__device__ float  g_qkv   [(size_t)MROWS * OPSZ];          // fp32 GEMM output
__device__ __half g_hs_h  [(size_t)MROWS * HID];           // fp16 hidden_states
__device__ __half g_wqkvt [(size_t)OPSZ * HID];            // Wqkv^T [n][k] fp16
__device__ __half g_wot   [(size_t)HID * HID];             // Wo^T   [n][k] fp16
__device__ __half g_qh    [(size_t)BATCH * NH  * SEQ * HD];
__device__ __half g_kh    [(size_t)BATCH * NKV * SEQ * HD];
__device__ __half g_vh    [(size_t)BATCH * NKV * SEQ * HD]; // TRANSPOSED [b,kvh][d][s]
__device__ __half g_att_h [(size_t)MROWS * HID];           // fp16 attention output

// ============================================================
//          FP16 MMA + ldmatrix + cp.async helpers
// ============================================================
__device__ __forceinline__ void mma_f16(float* c, const uint32_t* a, const uint32_t* b) {
    asm volatile(
        "mma.sync.aligned.m16n8k16.row.col.f32.f16.f16.f32 "
        "{%0,%1,%2,%3}, {%4,%5,%6,%7}, {%8,%9}, {%0,%1,%2,%3};\n"
        : "+f"(c[0]), "+f"(c[1]), "+f"(c[2]), "+f"(c[3])
        : "r"(a[0]), "r"(a[1]), "r"(a[2]), "r"(a[3]),
          "r"(b[0]), "r"(b[1]));
}

__device__ __forceinline__ void ldmx4(uint32_t* r, uint32_t addr) {
    asm volatile("ldmatrix.sync.aligned.m8n8.x4.shared.b16 {%0,%1,%2,%3}, [%4];"
        : "=r"(r[0]), "=r"(r[1]), "=r"(r[2]), "=r"(r[3]) : "r"(addr));
}

__device__ __forceinline__ void cp16(uint32_t dst, const void* src) {
    asm volatile("cp.async.cg.shared.global [%0], [%1], 16;" :: "r"(dst), "l"(src));
}
__device__ __forceinline__ void cp_commit() {
    asm volatile("cp.async.commit_group;");
}
template<int N> __device__ __forceinline__ void cp_wait() {
    asm volatile("cp.async.wait_group %0;" :: "n"(N));
}

// ============================================================
//            pre-pass kernels (fp32 -> fp16)
// ============================================================
__global__ __launch_bounds__(256) void half_copy_kernel(
    const float* __restrict__ src, __half* __restrict__ dst)
{
    int i = blockIdx.x * 256 + threadIdx.x;
    float4 v = ((const float4*)src)[i];
    half2 lo = __floats2half2_rn(v.x, v.y);
    half2 hi = __floats2half2_rn(v.z, v.w);
    ((half2*)dst)[2 * i]     = lo;
    ((half2*)dst)[2 * i + 1] = hi;
}

// dst[N][K] (fp16) = src[K][N] (fp32) transposed
__global__ __launch_bounds__(256) void transpose_half_kernel(
    const float* __restrict__ src, __half* __restrict__ dst, int K, int N)
{
    __shared__ float tile[32][33];
    const int n0 = blockIdx.x * 32;
    const int k0 = blockIdx.y * 32;
    const int tx = threadIdx.x & 31;
    const int ty = threadIdx.x >> 5;      // 0..7
    #pragma unroll
    for (int i = 0; i < 4; i++)
        tile[ty + 8 * i][tx] = src[(size_t)(k0 + ty + 8 * i) * N + n0 + tx];
    __syncthreads();
    #pragma unroll
    for (int i = 0; i < 4; i++)
        dst[(size_t)(n0 + ty + 8 * i) * K + k0 + tx] =
            __float2half_rn(tile[tx][ty + 8 * i]);
}

// ============================================================
//    FP16 GEMM, 3-stage cp.async pipeline + ldmatrix
//  C[M,N] (fp32) = A[M,K] @ Bt[N,K]^T, A/Bt fp16.
//  CTA 128x128x32, 8 warps (4m x 2n), warp tile 32x64.
// ============================================================
#define GBM 128
#define GBN 128
#define GBK 32
#define ROWB 80                 // 64B data + 16B pad (odd 16B units)
#define A_TILE_B (GBM * ROWB)   // 10240
#define STAGE_B  (2 * A_TILE_B) // 20480
#define NSTAGE 3
#define GEMM_SMEM_BYTES (NSTAGE * STAGE_B)   // 61440

__global__ __launch_bounds__(256, 2) void h16_gemm_kernel(
    const __half* __restrict__ A, const __half* __restrict__ Bt,
    float* __restrict__ C, int M, int N, int K)
{
    extern __shared__ __align__(16) char smg[];

    const int tid  = threadIdx.x;
    const int lane = tid & 31;
    const int wid  = tid >> 5;
    const int g    = lane >> 2;
    const int tg   = lane & 3;
    const int wm   = (wid & 3) * 32;
    const int wn   = (wid >> 2) * 64;

    const int bm = blockIdx.y * GBM;
    const int bn = blockIdx.x * GBN;

    // loader: thread covers rows r0, r0+64 of A and B; fixed 16B col chunk
    const int r0 = tid >> 2;            // 0..63
    const int ce = (tid & 3) * 8;       // fp16 element offset 0..24
    const __half* Ap[2];
    const __half* Bp[2];
    #pragma unroll
    for (int i = 0; i < 2; i++) {
        Ap[i] = A  + (size_t)(bm + r0 + 64 * i) * K + ce;
        Bp[i] = Bt + (size_t)(bn + r0 + 64 * i) * K + ce;
    }
    const uint32_t sm_base = (uint32_t)__cvta_generic_to_shared(smg);
    const uint32_t adst = sm_base + (uint32_t)(r0 * ROWB + (tid & 3) * 16);
    const uint32_t bdst = adst + A_TILE_B;

    // per-lane ldmatrix addresses (stage 0)
    const int l7 = lane & 7;
    const int l8 = (lane >> 3) & 1;
    const int l16 = lane >> 4;
    uint32_t aaddr[2], baddr[4];
    #pragma unroll
    for (int mt = 0; mt < 2; mt++)
        aaddr[mt] = sm_base + (uint32_t)((wm + mt * 16 + l8 * 8 + l7) * ROWB + l16 * 16);
    #pragma unroll
    for (int ntp = 0; ntp < 4; ntp++)
        baddr[ntp] = sm_base + A_TILE_B +
            (uint32_t)((wn + ntp * 16 + l16 * 8 + l7) * ROWB + l8 * 16);

    const int nk = K / GBK;

    // prologue: stages 0,1
    #pragma unroll
    for (int s = 0; s < 2; s++) {
        uint32_t so = s * STAGE_B;
        #pragma unroll
        for (int i = 0; i < 2; i++) {
            cp16(adst + so + i * (64 * ROWB), Ap[i] + s * GBK);
            cp16(bdst + so + i * (64 * ROWB), Bp[i] + s * GBK);
        }
        cp_commit();
    }

    float acc[2][8][4];
    #pragma unroll
    for (int mt = 0; mt < 2; mt++)
        #pragma unroll
        for (int nt = 0; nt < 8; nt++)
            #pragma unroll
            for (int e = 0; e < 4; e++) acc[mt][nt][e] = 0.f;

    for (int kt = 0; kt < nk; kt++) {
        cp_wait<1>();
        __syncthreads();

        // issue stage kt+2
        if (kt + 2 < nk) {
            uint32_t so = ((kt + 2) % NSTAGE) * STAGE_B;
            int ko = (kt + 2) * GBK;
            #pragma unroll
            for (int i = 0; i < 2; i++) {
                cp16(adst + so + i * (64 * ROWB), Ap[i] + ko);
                cp16(bdst + so + i * (64 * ROWB), Bp[i] + ko);
            }
        }
        cp_commit();

        // compute stage kt: 2 k-chunks of 16
        const uint32_t so = (kt % NSTAGE) * STAGE_B;
        #pragma unroll
        for (int kc = 0; kc < 2; kc++) {
            uint32_t af[2][4];
            ldmx4(af[0], aaddr[0] + so + kc * 32);
            ldmx4(af[1], aaddr[1] + so + kc * 32);
            #pragma unroll
            for (int ntp = 0; ntp < 4; ntp++) {
                uint32_t bf[4];
                ldmx4(bf, baddr[ntp] + so + kc * 32);
                mma_f16(acc[0][2 * ntp],     af[0], bf);
                mma_f16(acc[0][2 * ntp + 1], af[0], bf + 2);
                mma_f16(acc[1][2 * ntp],     af[1], bf);
                mma_f16(acc[1][2 * ntp + 1], af[1], bf + 2);
            }
        }
    }

    // epilogue (fp32)
    #pragma unroll
    for (int mt = 0; mt < 2; mt++) {
        int r = bm + wm + mt * 16 + g;
        #pragma unroll
        for (int nt = 0; nt < 8; nt++) {
            int c0 = bn + wn + nt * 8 + tg * 2;
            *(float2*)(C + (size_t)r * N + c0)       = make_float2(acc[mt][nt][0], acc[mt][nt][1]);
            *(float2*)(C + (size_t)(r + 8) * N + c0) = make_float2(acc[mt][nt][2], acc[mt][nt][3]);
        }
    }
}

// ============================ RoPE + split ============================
// Outputs fp16. V stored TRANSPOSED: g_vh[b,kvh][d][s]
__global__ __launch_bounds__(256) void rope_split_kernel(
    const float* __restrict__ qkv,
    __half* __restrict__ Qb, __half* __restrict__ Kb, __half* __restrict__ Vb)
{
    const int m = blockIdx.x;
    const int b = m >> 11;
    const int s = m & 2047;
    const int tid = threadIdx.x;

    __shared__ float cosr[48], sinr[48];
    if (tid < 48) {
        float invf = powf(10000.f, -((float)(2 * tid)) / 96.f);
        float ang  = (float)s * invf;
        cosr[tid] = cosf(ang);
        sinr[tid] = sinf(ang);
    }
    __syncthreads();

    const float* row = qkv + (size_t)m * OPSZ;

    for (int idx = tid; idx < (NH + NKV) * 48; idx += 256) {
        int hh = idx / 48;
        int j  = idx % 48;
        float c  = cosr[j];
        float sn = sinr[j];
        if (hh < NH) {
            float x1 = row[hh * HD + j];
            float x2 = row[hh * HD + j + 48];
            size_t base = ((size_t)(b * NH + hh)) * SEQ * HD + (size_t)s * HD;
            Qb[base + j]      = __float2half_rn((x1 * c - x2 * sn) * QK_SCALE);
            Qb[base + j + 48] = __float2half_rn((x2 * c + x1 * sn) * QK_SCALE);
        } else {
            int kh = hh - NH;
            float x1 = row[NH * HD + kh * HD + j];
            float x2 = row[NH * HD + kh * HD + j + 48];
            size_t base = ((size_t)(b * NKV + kh)) * SEQ * HD + (size_t)s * HD;
            Kb[base + j]      = __float2half_rn(x1 * c - x2 * sn);
            Kb[base + j + 48] = __float2half_rn(x2 * c + x1 * sn);
        }
    }
    for (int idx = tid; idx < NKV * HD; idx += 256) {
        int kh = idx / HD, d = idx % HD;
        Vb[((size_t)(b * NKV + kh) * HD + d) * SEQ + s] =
            __float2half_rn(row[NH * HD + NKV * HD + idx]);
    }
}

// ============================================================
//   FP16 tensor-core flash attention (ldmatrix + cp.async)
//  CTA = (64 q-rows, b*NH+h). 256 threads, 8 warps. 2 CTAs/SM.
// ============================================================
#define AT_BQ 64
#define AT_BK 64
#define QKB 208    // bytes/row: 192 data + 16 pad (13 units, odd)
#define VTB 144    // bytes/row: 128 data + 16 pad (9 units, odd)
#define PFB 144    // fp16 P row bytes: 128 data + 16 pad
#define PSW 68     // fp32 score stride (words)

// byte offsets in dynamic smem
#define OFF_Q  0
#define OFF_K  (OFF_Q + AT_BQ * QKB)            // 13312
#define OFF_V  (OFF_K + AT_BK * QKB)            // 26624
#define OFF_PF (OFF_V + HD * VTB)               // 40448
#define OFF_PS (OFF_PF + AT_BQ * PFB)           // 49664
#define OFF_ST (OFF_PS + AT_BQ * PSW * 4)       // 67072
#define ATTN_SMEM_BYTES (OFF_ST + 3 * AT_BQ * 4)  // 67840

__global__ __launch_bounds__(256, 2) void attn_h16_kernel(
    const __half* __restrict__ Q, const __half* __restrict__ K,
    const __half* __restrict__ V, __half* __restrict__ O)
{
    extern __shared__ __align__(16) char smc[];
    float*  p_s  = (float*)(smc + OFF_PS);
    float*  m_s  = (float*)(smc + OFF_ST);
    float*  l_s  = m_s + AT_BQ;
    float*  al_s = l_s + AT_BQ;

    const int tid  = threadIdx.x;
    const int lane = tid & 31;
    const int wid  = tid >> 5;
    const int g    = lane >> 2;
    const int tg   = lane & 3;
    const int wm   = (wid & 3) * 16;
    const int wn   = (wid >> 2) * 32;
    const int wnp  = (wid >> 2) * 48;

    const int tileq = (gridDim.x - 1) - blockIdx.x;   // heavy causal CTAs first
    const int bh = blockIdx.y;
    const int b  = bh >> 5;
    const int h  = bh & 31;
    const int kvh = h >> 2;
    const int q0 = tileq * AT_BQ;

    const __half* Qb = Q + (size_t)bh * SEQ * HD;
    const __half* Kb = K + (size_t)(b * NKV + kvh) * SEQ * HD;
    const __half* Vb = V + (size_t)(b * NKV + kvh) * HD * SEQ;  // [d][s]

    const uint32_t smb = (uint32_t)__cvta_generic_to_shared(smc);
    const uint32_t q_base = smb + OFF_Q;
    const uint32_t k_base = smb + OFF_K;
    const uint32_t v_base = smb + OFF_V;
    const uint32_t pf_base = smb + OFF_PF;

    // per-lane ldmatrix addresses
    const int l7 = lane & 7;
    const int l8 = (lane >> 3) & 1;
    const int l16 = lane >> 4;
    uint32_t qaddr = q_base + (uint32_t)((wm + l8 * 8 + l7) * QKB + l16 * 16);
    uint32_t paddr = pf_base + (uint32_t)((wm + l8 * 8 + l7) * PFB + l16 * 16);
    uint32_t kaddr[2], vaddr[3];
    #pragma unroll
    for (int ntp = 0; ntp < 2; ntp++)
        kaddr[ntp] = k_base + (uint32_t)((wn + ntp * 16 + l16 * 8 + l7) * QKB + l8 * 16);
    #pragma unroll
    for (int ntp = 0; ntp < 3; ntp++)
        vaddr[ntp] = v_base + (uint32_t)((wnp + ntp * 16 + l16 * 8 + l7) * VTB + l8 * 16);

    // ---- prologue: cp.async Q tile + K tile 0 (one group) ----
    // 64 rows x 12 chunks each for Q and K
    #pragma unroll
    for (int i = 0; i < 3; i++) {
        int f = tid + 256 * i;          // < 768
        int row = f / 12;
        int cc  = f % 12;
        cp16(q_base + (uint32_t)(row * QKB + cc * 16),
             Qb + (size_t)(q0 + row) * HD + cc * 8);
        cp16(k_base + (uint32_t)(row * QKB + cc * 16),
             Kb + (size_t)row * HD + cc * 8);
    }
    cp_commit();

    if (tid < AT_BQ) { m_s[tid] = -1e30f; l_s[tid] = 0.f; }

    float acc[6][4];
    #pragma unroll
    for (int nt = 0; nt < 6; nt++)
        #pragma unroll
        for (int e = 0; e < 4; e++) acc[nt][e] = 0.f;

    const int ntiles = tileq + 1;
    for (int t = 0; t < ntiles; t++) {
        const int k0 = t * AT_BK;
        __syncthreads();       // prev iter fully done

        // issue V_t (96 rows x 8 chunks); do NOT wait yet
        #pragma unroll
        for (int i = 0; i < 3; i++) {
            int f = tid + 256 * i;      // < 768
            int d = f >> 3;
            int cc = f & 7;
            cp16(v_base + (uint32_t)(d * VTB + cc * 16),
                 Vb + (size_t)d * SEQ + k0 + cc * 8);
        }
        cp_commit();

        cp_wait<1>();          // K_t (and Q) arrived
        __syncthreads();

        // ---- S = Q K^T via MMA: K=96 -> 6 chunks of 16 ----
        float s4[4][4];
        #pragma unroll
        for (int nt = 0; nt < 4; nt++)
            #pragma unroll
            for (int e = 0; e < 4; e++) s4[nt][e] = 0.f;

        #pragma unroll
        for (int kc = 0; kc < 6; kc++) {
            uint32_t a[4];
            ldmx4(a, qaddr + kc * 32);
            #pragma unroll
            for (int ntp = 0; ntp < 2; ntp++) {
                uint32_t bf[4];
                ldmx4(bf, kaddr[ntp] + kc * 32);
                mma_f16(s4[2 * ntp],     a, bf);
                mma_f16(s4[2 * ntp + 1], a, bf + 2);
            }
        }

        // ---- mask (diag tile) + store fp32 scores ----
        const bool diag = (t == tileq);
        const int row0 = q0 + wm + g;
        #pragma unroll
        for (int nt = 0; nt < 4; nt++) {
            int col = k0 + wn + nt * 8 + 2 * tg;
            float v0 = s4[nt][0], v1 = s4[nt][1];
            float v2 = s4[nt][2], v3 = s4[nt][3];
            if (diag) {
                if (col     > row0)     v0 = -1e30f;
                if (col + 1 > row0)     v1 = -1e30f;
                if (col     > row0 + 8) v2 = -1e30f;
                if (col + 1 > row0 + 8) v3 = -1e30f;
            }
            int c = wn + nt * 8 + 2 * tg;
            *(float2*)&p_s[(wm + g) * PSW + c]     = make_float2(v0, v1);
            *(float2*)&p_s[(wm + g + 8) * PSW + c] = make_float2(v2, v3);
        }
        __syncthreads();       // QK done -> k_s free; p_s visible

        // prefetch K_{t+1}, overlapped with softmax (+V in flight)
        if (t + 1 < ntiles) {
            const int k0n = k0 + AT_BK;
            #pragma unroll
            for (int i = 0; i < 3; i++) {
                int f = tid + 256 * i;
                int row = f / 12;
                int cc  = f % 12;
                cp16(k_base + (uint32_t)(row * QKB + cc * 16),
                     Kb + (size_t)(k0n + row) * HD + cc * 8);
            }
        }
        cp_commit();           // uniform group count

        // ---- online softmax: 4 threads per row; write fp16 P ----
        {
            const int r  = tid >> 2;
            const int qt = tid & 3;
            float* prow = &p_s[r * PSW + qt * 16];
            __half* pfrow = (__half*)(smc + OFF_PF + r * PFB) + qt * 16;
            float mold = m_s[r];
            float mt = mold;
            #pragma unroll
            for (int j = 0; j < 16; j++) mt = fmaxf(mt, prow[j]);
            mt = fmaxf(mt, __shfl_xor_sync(0xffffffffu, mt, 1));
            mt = fmaxf(mt, __shfl_xor_sync(0xffffffffu, mt, 2));
            float alpha = __expf(mold - mt);
            float sum = 0.f;
            #pragma unroll
            for (int j = 0; j < 16; j += 2) {
                float e0 = __expf(prow[j] - mt);
                float e1 = __expf(prow[j + 1] - mt);
                sum += e0 + e1;
                *(half2*)&pfrow[j] = __floats2half2_rn(e0, e1);
            }
            sum += __shfl_xor_sync(0xffffffffu, sum, 1);
            sum += __shfl_xor_sync(0xffffffffu, sum, 2);
            if (qt == 0) {
                m_s[r]  = mt;
                l_s[r]  = l_s[r] * alpha + sum;
                al_s[r] = alpha;
            }
        }

        cp_wait<1>();          // V_t arrived (K_{t+1} may stay pending)
        __syncthreads();       // v_s + pf_s + al_s visible

        // ---- rescale O accumulators ----
        {
            float a0 = al_s[wm + g];
            float a1 = al_s[wm + g + 8];
            #pragma unroll
            for (int nt = 0; nt < 6; nt++) {
                acc[nt][0] *= a0; acc[nt][1] *= a0;
                acc[nt][2] *= a1; acc[nt][3] *= a1;
            }
        }

        // ---- O += P V via MMA: K=64 -> 4 chunks of 16 ----
        #pragma unroll
        for (int kc = 0; kc < 4; kc++) {
            uint32_t a[4];
            ldmx4(a, paddr + kc * 32);
            #pragma unroll
            for (int ntp = 0; ntp < 3; ntp++) {
                uint32_t bf[4];
                ldmx4(bf, vaddr[ntp] + kc * 32);
                mma_f16(acc[2 * ntp],     a, bf);
                mma_f16(acc[2 * ntp + 1], a, bf + 2);
            }
        }
    }

    // ---- epilogue: normalize, write fp16 att (O-proj A operand) ----
    {
        const int r0 = wm + g;
        const float inv0 = 1.f / l_s[r0];
        const float inv1 = 1.f / l_s[r0 + 8];
        size_t base0 = ((size_t)(b * SEQ + q0 + r0)) * HID + h * HD;
        size_t base1 = base0 + 8 * HID;
        #pragma unroll
        for (int nt = 0; nt < 6; nt++) {
            int c = wnp + nt * 8 + 2 * tg;
            *(half2*)(O + base0 + c) =
                __floats2half2_rn(acc[nt][0] * inv0, acc[nt][1] * inv0);
            *(half2*)(O + base1 + c) =
                __floats2half2_rn(acc[nt][2] * inv1, acc[nt][3] * inv1);
        }
    }
}

// ============================ launch ============================
extern "C" void kernel_launch(void* const* d_in, const int* in_sizes, int n_in,
                              void* d_out, int out_size)
{
    const float* hs   = (const float*)d_in[0];   // hidden_states
    // d_in[1] = position_ids (arange, unused)
    // d_in[2] = attention_mask (causal, unused)
    const float* Wqkv = (const float*)d_in[3];
    const float* Wo   = (const float*)d_in[4];
    float* out = (float*)d_out;

    float *qkv;
    __half *hs_h, *wqkvt, *wot, *Qh, *Kh, *Vh, *att_h;
    cudaGetSymbolAddress((void**)&qkv,   g_qkv);
    cudaGetSymbolAddress((void**)&hs_h,  g_hs_h);
    cudaGetSymbolAddress((void**)&wqkvt, g_wqkvt);
    cudaGetSymbolAddress((void**)&wot,   g_wot);
    cudaGetSymbolAddress((void**)&Qh,    g_qh);
    cudaGetSymbolAddress((void**)&Kh,    g_kh);
    cudaGetSymbolAddress((void**)&Vh,    g_vh);
    cudaGetSymbolAddress((void**)&att_h, g_att_h);

    cudaFuncSetAttribute(h16_gemm_kernel,
                         cudaFuncAttributeMaxDynamicSharedMemorySize,
                         GEMM_SMEM_BYTES);
    cudaFuncSetAttribute(attn_h16_kernel,
                         cudaFuncAttributeMaxDynamicSharedMemorySize,
                         ATTN_SMEM_BYTES);

    // 0) fp32 -> fp16 pre-pass: hidden_states copy; weights transpose
    half_copy_kernel<<<(MROWS * HID / 4) / 256, 256>>>(hs, hs_h);
    transpose_half_kernel<<<dim3(OPSZ / 32, HID / 32), 256>>>(Wqkv, wqkvt, HID, OPSZ);
    transpose_half_kernel<<<dim3(HID / 32, HID / 32), 256>>>(Wo, wot, HID, HID);

    // 1) QKV projection (fp16 MMA, cp.async pipeline) -> fp32 qkv
    h16_gemm_kernel<<<dim3(OPSZ / GBN, MROWS / GBM), 256, GEMM_SMEM_BYTES>>>(
        hs_h, wqkvt, qkv, MROWS, OPSZ, HID);

    // 2) RoPE + split -> fp16 Q/K, fp16 V transposed [d][s]
    rope_split_kernel<<<MROWS, 256>>>(qkv, Qh, Kh, Vh);

    // 3) causal GQA flash attention (fp16 MMA) -> fp16 att
    attn_h16_kernel<<<dim3(SEQ / AT_BQ, BATCH * NH), 256, ATTN_SMEM_BYTES>>>(
        Qh, Kh, Vh, att_h);

    // 4) output projection (fp16 MMA) -> fp32 out
    h16_gemm_kernel<<<dim3(HID / GBN, MROWS / GBM), 256, GEMM_SMEM_BYTES>>>(
        att_h, wot, out, MROWS, HID, HID);
}

// round 17
// speedup vs baseline: 2.1029x; 1.1362x over previous
#include <cuda_runtime.h>
#include <cuda_fp16.h>
#include <math.h>
#include <stdint.h>
#include <string.h>

// Problem constants
#define BATCH   2
#define SEQ     2048
#define HID     3072
#define NH      32
#define NKV     8
#define HD      96
#define OPSZ    4608          // NH*HD + 2*NKV*HD
#define MROWS   4096          // BATCH*SEQ
#define QK_SCALE 0.10206207261596577f  // 1/sqrt(96)

// ---------------- scratch (device globals, no allocation) ----------------
__device__ float  g_qkv   [(size_t)MROWS * OPSZ];          // fp32 GEMM output
__device__ __half g_hs_h  [(size_t)MROWS * HID];           // fp16 hidden_states
__device__ __half g_wqkvt [(size_t)OPSZ * HID];            // Wqkv^T [n][k] fp16
__device__ __half g_wot   [(size_t)HID * HID];             // Wo^T   [n][k] fp16
__device__ __half g_qh    [(size_t)BATCH * NH  * SEQ * HD];
__device__ __half g_kh    [(size_t)BATCH * NKV * SEQ * HD];
__device__ __half g_vh    [(size_t)BATCH * NKV * SEQ * HD]; // TRANSPOSED [b,kvh][d][s]
__device__ __half g_att_h [(size_t)MROWS * HID];           // fp16 attention output

// ============================================================
//          FP16 MMA + ldmatrix + cp.async helpers
// ============================================================
__device__ __forceinline__ uint32_t h2u(__half2 h) {
    uint32_t u;
    memcpy(&u, &h, 4);
    return u;
}

__device__ __forceinline__ void mma_f16(float* c, const uint32_t* a, const uint32_t* b) {
    asm volatile(
        "mma.sync.aligned.m16n8k16.row.col.f32.f16.f16.f32 "
        "{%0,%1,%2,%3}, {%4,%5,%6,%7}, {%8,%9}, {%0,%1,%2,%3};\n"
        : "+f"(c[0]), "+f"(c[1]), "+f"(c[2]), "+f"(c[3])
        : "r"(a[0]), "r"(a[1]), "r"(a[2]), "r"(a[3]),
          "r"(b[0]), "r"(b[1]));
}

__device__ __forceinline__ void ldmx4(uint32_t* r, uint32_t addr) {
    asm volatile("ldmatrix.sync.aligned.m8n8.x4.shared.b16 {%0,%1,%2,%3}, [%4];"
        : "=r"(r[0]), "=r"(r[1]), "=r"(r[2]), "=r"(r[3]) : "r"(addr));
}

__device__ __forceinline__ void cp16(uint32_t dst, const void* src) {
    asm volatile("cp.async.cg.shared.global [%0], [%1], 16;" :: "r"(dst), "l"(src));
}
__device__ __forceinline__ void cp_commit() {
    asm volatile("cp.async.commit_group;");
}
template<int N> __device__ __forceinline__ void cp_wait() {
    asm volatile("cp.async.wait_group %0;" :: "n"(N));
}

// ============================================================
//            pre-pass kernels (fp32 -> fp16)
// ============================================================
__global__ __launch_bounds__(256) void half_copy_kernel(
    const float* __restrict__ src, __half* __restrict__ dst)
{
    int i = blockIdx.x * 256 + threadIdx.x;
    float4 v = ((const float4*)src)[i];
    half2 lo = __floats2half2_rn(v.x, v.y);
    half2 hi = __floats2half2_rn(v.z, v.w);
    ((half2*)dst)[2 * i]     = lo;
    ((half2*)dst)[2 * i + 1] = hi;
}

// dst[N][K] (fp16) = src[K][N] (fp32) transposed
__global__ __launch_bounds__(256) void transpose_half_kernel(
    const float* __restrict__ src, __half* __restrict__ dst, int K, int N)
{
    __shared__ float tile[32][33];
    const int n0 = blockIdx.x * 32;
    const int k0 = blockIdx.y * 32;
    const int tx = threadIdx.x & 31;
    const int ty = threadIdx.x >> 5;      // 0..7
    #pragma unroll
    for (int i = 0; i < 4; i++)
        tile[ty + 8 * i][tx] = src[(size_t)(k0 + ty + 8 * i) * N + n0 + tx];
    __syncthreads();
    #pragma unroll
    for (int i = 0; i < 4; i++)
        dst[(size_t)(n0 + ty + 8 * i) * K + k0 + tx] =
            __float2half_rn(tile[tx][ty + 8 * i]);
}

// ============================================================
//    FP16 GEMM, 3-stage cp.async pipeline + ldmatrix
//  C[M,N] (fp32) = A[M,K] @ Bt[N,K]^T, A/Bt fp16.  (1059us-proven)
// ============================================================
#define GBM 128
#define GBN 128
#define GBK 32
#define ROWB 80                 // 64B data + 16B pad (odd 16B units)
#define A_TILE_B (GBM * ROWB)   // 10240
#define STAGE_B  (2 * A_TILE_B) // 20480
#define NSTAGE 3
#define GEMM_SMEM_BYTES (NSTAGE * STAGE_B)   // 61440

__global__ __launch_bounds__(256, 2) void h16_gemm_kernel(
    const __half* __restrict__ A, const __half* __restrict__ Bt,
    float* __restrict__ C, int M, int N, int K)
{
    extern __shared__ __align__(16) char smg[];

    const int tid  = threadIdx.x;
    const int lane = tid & 31;
    const int wid  = tid >> 5;
    const int g    = lane >> 2;
    const int tg   = lane & 3;
    const int wm   = (wid & 3) * 32;
    const int wn   = (wid >> 2) * 64;

    const int bm = blockIdx.y * GBM;
    const int bn = blockIdx.x * GBN;

    const int r0 = tid >> 2;            // 0..63
    const int ce = (tid & 3) * 8;
    const __half* Ap[2];
    const __half* Bp[2];
    #pragma unroll
    for (int i = 0; i < 2; i++) {
        Ap[i] = A  + (size_t)(bm + r0 + 64 * i) * K + ce;
        Bp[i] = Bt + (size_t)(bn + r0 + 64 * i) * K + ce;
    }
    const uint32_t sm_base = (uint32_t)__cvta_generic_to_shared(smg);
    const uint32_t adst = sm_base + (uint32_t)(r0 * ROWB + (tid & 3) * 16);
    const uint32_t bdst = adst + A_TILE_B;

    const int l7 = lane & 7;
    const int l8 = (lane >> 3) & 1;
    const int l16 = lane >> 4;
    uint32_t aaddr[2], baddr[4];
    #pragma unroll
    for (int mt = 0; mt < 2; mt++)
        aaddr[mt] = sm_base + (uint32_t)((wm + mt * 16 + l8 * 8 + l7) * ROWB + l16 * 16);
    #pragma unroll
    for (int ntp = 0; ntp < 4; ntp++)
        baddr[ntp] = sm_base + A_TILE_B +
            (uint32_t)((wn + ntp * 16 + l16 * 8 + l7) * ROWB + l8 * 16);

    const int nk = K / GBK;

    #pragma unroll
    for (int s = 0; s < 2; s++) {
        uint32_t so = s * STAGE_B;
        #pragma unroll
        for (int i = 0; i < 2; i++) {
            cp16(adst + so + i * (64 * ROWB), Ap[i] + s * GBK);
            cp16(bdst + so + i * (64 * ROWB), Bp[i] + s * GBK);
        }
        cp_commit();
    }

    float acc[2][8][4];
    #pragma unroll
    for (int mt = 0; mt < 2; mt++)
        #pragma unroll
        for (int nt = 0; nt < 8; nt++)
            #pragma unroll
            for (int e = 0; e < 4; e++) acc[mt][nt][e] = 0.f;

    for (int kt = 0; kt < nk; kt++) {
        cp_wait<1>();
        __syncthreads();

        if (kt + 2 < nk) {
            uint32_t so = ((kt + 2) % NSTAGE) * STAGE_B;
            int ko = (kt + 2) * GBK;
            #pragma unroll
            for (int i = 0; i < 2; i++) {
                cp16(adst + so + i * (64 * ROWB), Ap[i] + ko);
                cp16(bdst + so + i * (64 * ROWB), Bp[i] + ko);
            }
        }
        cp_commit();

        const uint32_t so = (kt % NSTAGE) * STAGE_B;
        #pragma unroll
        for (int kc = 0; kc < 2; kc++) {
            uint32_t af[2][4];
            ldmx4(af[0], aaddr[0] + so + kc * 32);
            ldmx4(af[1], aaddr[1] + so + kc * 32);
            #pragma unroll
            for (int ntp = 0; ntp < 4; ntp++) {
                uint32_t bf[4];
                ldmx4(bf, baddr[ntp] + so + kc * 32);
                mma_f16(acc[0][2 * ntp],     af[0], bf);
                mma_f16(acc[0][2 * ntp + 1], af[0], bf + 2);
                mma_f16(acc[1][2 * ntp],     af[1], bf);
                mma_f16(acc[1][2 * ntp + 1], af[1], bf + 2);
            }
        }
    }

    #pragma unroll
    for (int mt = 0; mt < 2; mt++) {
        int r = bm + wm + mt * 16 + g;
        #pragma unroll
        for (int nt = 0; nt < 8; nt++) {
            int c0 = bn + wn + nt * 8 + tg * 2;
            *(float2*)(C + (size_t)r * N + c0)       = make_float2(acc[mt][nt][0], acc[mt][nt][1]);
            *(float2*)(C + (size_t)(r + 8) * N + c0) = make_float2(acc[mt][nt][2], acc[mt][nt][3]);
        }
    }
}

// ============================ RoPE + split ============================
__global__ __launch_bounds__(256) void rope_split_kernel(
    const float* __restrict__ qkv,
    __half* __restrict__ Qb, __half* __restrict__ Kb, __half* __restrict__ Vb)
{
    const int m = blockIdx.x;
    const int b = m >> 11;
    const int s = m & 2047;
    const int tid = threadIdx.x;

    __shared__ float cosr[48], sinr[48];
    if (tid < 48) {
        float invf = powf(10000.f, -((float)(2 * tid)) / 96.f);
        float ang  = (float)s * invf;
        cosr[tid] = cosf(ang);
        sinr[tid] = sinf(ang);
    }
    __syncthreads();

    const float* row = qkv + (size_t)m * OPSZ;

    for (int idx = tid; idx < (NH + NKV) * 48; idx += 256) {
        int hh = idx / 48;
        int j  = idx % 48;
        float c  = cosr[j];
        float sn = sinr[j];
        if (hh < NH) {
            float x1 = row[hh * HD + j];
            float x2 = row[hh * HD + j + 48];
            size_t base = ((size_t)(b * NH + hh)) * SEQ * HD + (size_t)s * HD;
            Qb[base + j]      = __float2half_rn((x1 * c - x2 * sn) * QK_SCALE);
            Qb[base + j + 48] = __float2half_rn((x2 * c + x1 * sn) * QK_SCALE);
        } else {
            int kh = hh - NH;
            float x1 = row[NH * HD + kh * HD + j];
            float x2 = row[NH * HD + kh * HD + j + 48];
            size_t base = ((size_t)(b * NKV + kh)) * SEQ * HD + (size_t)s * HD;
            Kb[base + j]      = __float2half_rn(x1 * c - x2 * sn);
            Kb[base + j + 48] = __float2half_rn(x2 * c + x1 * sn);
        }
    }
    for (int idx = tid; idx < NKV * HD; idx += 256) {
        int kh = idx / HD, d = idx % HD;
        Vb[((size_t)(b * NKV + kh) * HD + d) * SEQ + s] =
            __float2half_rn(row[NH * HD + NKV * HD + idx]);
    }
}

// ============================================================
//   FP16 flash attention, FA2-style register softmax
//  CTA = (64 q-rows, b*NH+h). 128 threads, 4 warps, 3 CTAs/SM.
//  Warp owns 16 full rows: softmax = quad shuffles only.
//  P stays in registers (QK accumulator == PV A-operand layout).
//  K double-buffered; V wait deferred behind softmax.
// ============================================================
#define AT_BQ 64
#define AT_BK 64
#define QKB 208    // bytes/row: 192 data + 16 pad (13 units, odd)
#define VTB 144    // bytes/row: 128 data + 16 pad (9 units, odd)

#define OFF_Q  0
#define OFF_K0 (AT_BQ * QKB)                 // 13312
#define KBUF_B (AT_BK * QKB)                 // 13312
#define OFF_V  (OFF_K0 + 2 * KBUF_B)         // 39936
#define ATTN_SMEM_BYTES (OFF_V + HD * VTB)   // 53760

__global__ __launch_bounds__(128, 3) void attn_reg_kernel(
    const __half* __restrict__ Q, const __half* __restrict__ K,
    const __half* __restrict__ V, __half* __restrict__ O)
{
    extern __shared__ __align__(16) char smc[];

    const int tid  = threadIdx.x;
    const int lane = tid & 31;
    const int wid  = tid >> 5;          // 0..3
    const int g    = lane >> 2;
    const int tg   = lane & 3;
    const int wm   = wid * 16;          // warp owns rows wm..wm+15

    const int tileq = (gridDim.x - 1) - blockIdx.x;   // heavy causal CTAs first
    const int bh = blockIdx.y;
    const int b  = bh >> 5;
    const int h  = bh & 31;
    const int kvh = h >> 2;
    const int q0 = tileq * AT_BQ;

    const __half* Qb = Q + (size_t)bh * SEQ * HD;
    const __half* Kb = K + (size_t)(b * NKV + kvh) * SEQ * HD;
    const __half* Vb = V + (size_t)(b * NKV + kvh) * HD * SEQ;  // [d][s]

    const uint32_t smb = (uint32_t)__cvta_generic_to_shared(smc);
    const uint32_t q_base = smb + OFF_Q;
    const uint32_t k_base = smb + OFF_K0;
    const uint32_t v_base = smb + OFF_V;

    // per-lane ldmatrix addresses
    const int l7 = lane & 7;
    const int l8 = (lane >> 3) & 1;
    const int l16 = lane >> 4;
    const uint32_t qaddr = q_base + (uint32_t)((wm + l8 * 8 + l7) * QKB + l16 * 16);
    uint32_t kaddr[4], vaddr[6];
    #pragma unroll
    for (int ntp = 0; ntp < 4; ntp++)
        kaddr[ntp] = k_base + (uint32_t)((ntp * 16 + l16 * 8 + l7) * QKB + l8 * 16);
    #pragma unroll
    for (int ntp = 0; ntp < 6; ntp++)
        vaddr[ntp] = v_base + (uint32_t)((ntp * 16 + l16 * 8 + l7) * VTB + l8 * 16);

    // ---- prologue: Q tile + K tile 0 (one group); 64 rows x 12 chunks ----
    #pragma unroll
    for (int i = 0; i < 6; i++) {
        int f = tid + 128 * i;          // < 768
        int row = f / 12;
        int cc  = f % 12;
        cp16(q_base + (uint32_t)(row * QKB + cc * 16),
             Qb + (size_t)(q0 + row) * HD + cc * 8);
        cp16(k_base + (uint32_t)(row * QKB + cc * 16),
             Kb + (size_t)row * HD + cc * 8);
    }
    cp_commit();

    float m0 = -1e30f, m1 = -1e30f, l0 = 0.f, l1 = 0.f;
    float acc[12][4];
    #pragma unroll
    for (int nt = 0; nt < 12; nt++)
        #pragma unroll
        for (int e = 0; e < 4; e++) acc[nt][e] = 0.f;

    const int ntiles = tileq + 1;
    for (int t = 0; t < ntiles; t++) {
        const int k0 = t * AT_BK;
        __syncthreads();       // prev iter fully done (V + old-K buffers free)

        // issue V_t (group); 96 rows x 8 chunks
        #pragma unroll
        for (int i = 0; i < 6; i++) {
            int f = tid + 128 * i;      // < 768
            int d = f >> 3;
            int cc = f & 7;
            cp16(v_base + (uint32_t)(d * VTB + cc * 16),
                 Vb + (size_t)d * SEQ + k0 + cc * 8);
        }
        cp_commit();

        // issue K_{t+1} into the other K buffer (group; empty on last iter)
        if (t + 1 < ntiles) {
            const uint32_t kb_next = k_base + (uint32_t)(((t + 1) & 1) * KBUF_B);
            const int k0n = k0 + AT_BK;
            #pragma unroll
            for (int i = 0; i < 6; i++) {
                int f = tid + 128 * i;
                int row = f / 12;
                int cc  = f % 12;
                cp16(kb_next + (uint32_t)(row * QKB + cc * 16),
                     Kb + (size_t)(k0n + row) * HD + cc * 8);
            }
        }
        cp_commit();

        cp_wait<2>();          // K_t (and Q) arrived; V_t / K_{t+1} may pend
        __syncthreads();

        // ---- S = Q K^T: full 64-wide tile per warp, K=96 (6 chunks) ----
        const uint32_t kb_off = (uint32_t)((t & 1) * KBUF_B);
        float s4[8][4];
        #pragma unroll
        for (int nt = 0; nt < 8; nt++)
            #pragma unroll
            for (int e = 0; e < 4; e++) s4[nt][e] = 0.f;

        #pragma unroll
        for (int kc = 0; kc < 6; kc++) {
            uint32_t a[4];
            ldmx4(a, qaddr + kc * 32);
            #pragma unroll
            for (int ntp = 0; ntp < 4; ntp++) {
                uint32_t bf[4];
                ldmx4(bf, kaddr[ntp] + kb_off + kc * 32);
                mma_f16(s4[2 * ntp],     a, bf);
                mma_f16(s4[2 * ntp + 1], a, bf + 2);
            }
        }

        // ---- mask (diag tile) ----
        const bool diag = (t == tileq);
        const int row0 = q0 + wm + g;
        if (diag) {
            #pragma unroll
            for (int nt = 0; nt < 8; nt++) {
                int col = k0 + nt * 8 + 2 * tg;
                if (col     > row0)     s4[nt][0] = -1e30f;
                if (col + 1 > row0)     s4[nt][1] = -1e30f;
                if (col     > row0 + 8) s4[nt][2] = -1e30f;
                if (col + 1 > row0 + 8) s4[nt][3] = -1e30f;
            }
        }

        // ---- register softmax (quad shuffles; warp owns full rows) ----
        float mx0 = m0, mx1 = m1;
        #pragma unroll
        for (int nt = 0; nt < 8; nt++) {
            mx0 = fmaxf(mx0, fmaxf(s4[nt][0], s4[nt][1]));
            mx1 = fmaxf(mx1, fmaxf(s4[nt][2], s4[nt][3]));
        }
        mx0 = fmaxf(mx0, __shfl_xor_sync(0xffffffffu, mx0, 1));
        mx0 = fmaxf(mx0, __shfl_xor_sync(0xffffffffu, mx0, 2));
        mx1 = fmaxf(mx1, __shfl_xor_sync(0xffffffffu, mx1, 1));
        mx1 = fmaxf(mx1, __shfl_xor_sync(0xffffffffu, mx1, 2));

        const float al0 = __expf(m0 - mx0);
        const float al1 = __expf(m1 - mx1);
        float sum0 = 0.f, sum1 = 0.f;
        uint32_t plo[8], phi[8];       // fp16x2 P: rows g / g+8
        #pragma unroll
        for (int nt = 0; nt < 8; nt++) {
            float e0 = __expf(s4[nt][0] - mx0);
            float e1 = __expf(s4[nt][1] - mx0);
            float e2 = __expf(s4[nt][2] - mx1);
            float e3 = __expf(s4[nt][3] - mx1);
            sum0 += e0 + e1;
            sum1 += e2 + e3;
            plo[nt] = h2u(__floats2half2_rn(e0, e1));
            phi[nt] = h2u(__floats2half2_rn(e2, e3));
        }
        sum0 += __shfl_xor_sync(0xffffffffu, sum0, 1);
        sum0 += __shfl_xor_sync(0xffffffffu, sum0, 2);
        sum1 += __shfl_xor_sync(0xffffffffu, sum1, 1);
        sum1 += __shfl_xor_sync(0xffffffffu, sum1, 2);

        m0 = mx0; m1 = mx1;
        l0 = l0 * al0 + sum0;
        l1 = l1 * al1 + sum1;
        #pragma unroll
        for (int nt = 0; nt < 12; nt++) {
            acc[nt][0] *= al0; acc[nt][1] *= al0;
            acc[nt][2] *= al1; acc[nt][3] *= al1;
        }

        cp_wait<1>();          // V_t arrived (K_{t+1} may stay pending)
        __syncthreads();

        // ---- O += P V: P in registers, K=64 (4 chunks), n=96 ----
        #pragma unroll
        for (int kc = 0; kc < 4; kc++) {
            uint32_t a[4] = { plo[2 * kc], phi[2 * kc],
                              plo[2 * kc + 1], phi[2 * kc + 1] };
            #pragma unroll
            for (int ntp = 0; ntp < 6; ntp++) {
                uint32_t bf[4];
                ldmx4(bf, vaddr[ntp] + kc * 32);
                mma_f16(acc[2 * ntp],     a, bf);
                mma_f16(acc[2 * ntp + 1], a, bf + 2);
            }
        }
    }

    // ---- epilogue: normalize, write fp16 att ----
    {
        const float inv0 = 1.f / l0;
        const float inv1 = 1.f / l1;
        size_t base0 = ((size_t)(b * SEQ + q0 + wm + g)) * HID + h * HD;
        size_t base1 = base0 + 8 * HID;
        #pragma unroll
        for (int nt = 0; nt < 12; nt++) {
            int c = nt * 8 + 2 * tg;
            *(half2*)(O + base0 + c) =
                __floats2half2_rn(acc[nt][0] * inv0, acc[nt][1] * inv0);
            *(half2*)(O + base1 + c) =
                __floats2half2_rn(acc[nt][2] * inv1, acc[nt][3] * inv1);
        }
    }
}

// ============================ launch ============================
extern "C" void kernel_launch(void* const* d_in, const int* in_sizes, int n_in,
                              void* d_out, int out_size)
{
    const float* hs   = (const float*)d_in[0];   // hidden_states
    // d_in[1] = position_ids (arange, unused)
    // d_in[2] = attention_mask (causal, unused)
    const float* Wqkv = (const float*)d_in[3];
    const float* Wo   = (const float*)d_in[4];
    float* out = (float*)d_out;

    float *qkv;
    __half *hs_h, *wqkvt, *wot, *Qh, *Kh, *Vh, *att_h;
    cudaGetSymbolAddress((void**)&qkv,   g_qkv);
    cudaGetSymbolAddress((void**)&hs_h,  g_hs_h);
    cudaGetSymbolAddress((void**)&wqkvt, g_wqkvt);
    cudaGetSymbolAddress((void**)&wot,   g_wot);
    cudaGetSymbolAddress((void**)&Qh,    g_qh);
    cudaGetSymbolAddress((void**)&Kh,    g_kh);
    cudaGetSymbolAddress((void**)&Vh,    g_vh);
    cudaGetSymbolAddress((void**)&att_h, g_att_h);

    cudaFuncSetAttribute(h16_gemm_kernel,
                         cudaFuncAttributeMaxDynamicSharedMemorySize,
                         GEMM_SMEM_BYTES);
    cudaFuncSetAttribute(attn_reg_kernel,
                         cudaFuncAttributeMaxDynamicSharedMemorySize,
                         ATTN_SMEM_BYTES);

    // 0) fp32 -> fp16 pre-pass: hidden_states copy; weights transpose
    half_copy_kernel<<<(MROWS * HID / 4) / 256, 256>>>(hs, hs_h);
    transpose_half_kernel<<<dim3(OPSZ / 32, HID / 32), 256>>>(Wqkv, wqkvt, HID, OPSZ);
    transpose_half_kernel<<<dim3(HID / 32, HID / 32), 256>>>(Wo, wot, HID, HID);

    // 1) QKV projection (fp16 MMA, cp.async pipeline) -> fp32 qkv
    h16_gemm_kernel<<<dim3(OPSZ / GBN, MROWS / GBM), 256, GEMM_SMEM_BYTES>>>(
        hs_h, wqkvt, qkv, MROWS, OPSZ, HID);

    // 2) RoPE + split -> fp16 Q/K, fp16 V transposed [d][s]
    rope_split_kernel<<<MROWS, 256>>>(qkv, Qh, Kh, Vh);

    // 3) causal GQA flash attention (register softmax) -> fp16 att
    attn_reg_kernel<<<dim3(SEQ / AT_BQ, BATCH * NH), 128, ATTN_SMEM_BYTES>>>(
        Qh, Kh, Vh, att_h);

    // 4) output projection (fp16 MMA) -> fp32 out
    h16_gemm_kernel<<<dim3(HID / GBN, MROWS / GBM), 256, GEMM_SMEM_BYTES>>>(
        att_h, wot, out, MROWS, HID, HID);
}